// round 4
// baseline (speedup 1.0000x reference)
#include <cuda_runtime.h>

#define BATCH 16384
#define STEPS 32
#define LAT   64
#define IN_W  (STEPS * (2 * LAT + 1) + 2 * LAT)   // 4256 floats per row
#define WARPS_PER_BLOCK 8
#define NTHREADS (WARPS_PER_BLOCK * 32)
#define NBLOCKS (BATCH / WARPS_PER_BLOCK)          // 2048

// scratch for deterministic two-stage loss reduction (no allocations allowed)
__device__ float g_partials[NBLOCKS];

__global__ void __launch_bounds__(NTHREADS)
planar_flow_kernel(const float* __restrict__ in,
                   const float* __restrict__ noise,
                   float* __restrict__ out)
{
    const int warp = threadIdx.x >> 5;
    const int lane = threadIdx.x & 31;
    const int row  = blockIdx.x * WARPS_PER_BLOCK + warp;

    const float*  rp  = in + (size_t)row * IN_W;
    const float2* rp2 = (const float2*)rp;                       // row is 8B-aligned (4256*4 % 8 == 0)

    // --- z0 = mu + noise * exp(0.5*logsigma2) ---
    float2 mu = rp2[lane];            // floats [0,64)
    float2 ls = rp2[32 + lane];       // floats [64,128)
    const float2* np2 = (const float2*)(noise + (size_t)row * LAT);
    float2 nz = np2[lane];

    float2 z;
    z.x = mu.x + nz.x * expf(0.5f * ls.x);
    z.y = mu.y + nz.y * expf(0.5f * ls.y);

    // per-lane KL partial: -0.5*(n^2 + logsigma2) over this lane's 2 elements
    float kl_part = -0.5f * (nz.x * nz.x + nz.y * nz.y + ls.x + ls.y);

    // biases: floats [4224, 4256); lane s holds bias for step s
    float bias_reg = rp[(2 + 2 * STEPS) * LAT + lane];

    // U region starts at float 128 (float2 idx 64-per... stride 32 float2 per step)
    const float2* U2 = (const float2*)(rp + 2 * LAT);
    const float2* W2 = (const float2*)(rp + (2 + STEPS) * LAT);

    float2 u = U2[lane];
    float2 w = W2[lane];

    float logacc = 0.0f;   // identical across lanes after butterflies

    #pragma unroll 4
    for (int s = 0; s < STEPS; s++) {
        // prefetch next step's u,w while this step's dependent chain runs
        int sn = (s + 1 < STEPS) ? (s + 1) : s;
        float2 un = U2[sn * 32 + lane];
        float2 wn = W2[sn * 32 + lane];

        float hl = w.x * z.x + w.y * z.y;     // partial of w . z
        float ul = u.x * w.x + u.y * w.y;     // partial of u . w

        #pragma unroll
        for (int o = 16; o > 0; o >>= 1) {
            hl += __shfl_xor_sync(0xffffffffu, hl, o);
            ul += __shfl_xor_sync(0xffffffffu, ul, o);
        }

        float bb = __shfl_sync(0xffffffffu, bias_reg, s);
        float t  = tanhf(hl + bb);
        float x  = (1.0f - t * t) * ul + 1.0f;
        logacc  -= logf(fabsf(x));

        z.x += u.x * t;
        z.y += u.y * t;

        u = un; w = wn;
    }

    // write z (coalesced float2)
    ((float2*)out)[(size_t)row * 32 + lane] = z;

    // reduce kl_part across the warp; logacc is already warp-uniform
    #pragma unroll
    for (int o = 16; o > 0; o >>= 1)
        kl_part += __shfl_xor_sync(0xffffffffu, kl_part, o);

    float row_term = kl_part + logacc;

    __shared__ float sacc[WARPS_PER_BLOCK];
    if (lane == 0) sacc[warp] = row_term;
    __syncthreads();
    if (threadIdx.x == 0) {
        float s = 0.0f;
        #pragma unroll
        for (int i = 0; i < WARPS_PER_BLOCK; i++) s += sacc[i];
        g_partials[blockIdx.x] = s;
    }
}

__global__ void __launch_bounds__(1024)
loss_reduce_kernel(float* __restrict__ out, int out_size)
{
    __shared__ float sh[1024];
    int tid = threadIdx.x;
    float v = g_partials[tid] + g_partials[tid + 1024];   // NBLOCKS == 2048
    sh[tid] = v;
    __syncthreads();
    #pragma unroll
    for (int o = 512; o > 0; o >>= 1) {
        if (tid < o) sh[tid] += sh[tid + o];
        __syncthreads();
    }
    if (tid == 0) out[out_size - 1] = sh[0] * (1.0f / (float)BATCH);
}

extern "C" void kernel_launch(void* const* d_in, const int* in_sizes, int n_in,
                              void* d_out, int out_size)
{
    const float* in    = (const float*)d_in[0];
    const float* noise = (const float*)d_in[1];
    float*       out   = (float*)d_out;

    planar_flow_kernel<<<NBLOCKS, NTHREADS>>>(in, noise, out);
    loss_reduce_kernel<<<1, 1024>>>(out, out_size);
}

// round 7
// speedup vs baseline: 1.3967x; 1.3967x over previous
#include <cuda_runtime.h>

#define BATCH 16384
#define STEPS 32
#define LAT   64
#define IN_W  (STEPS * (2 * LAT + 1) + 2 * LAT)   // 4256 floats per row
#define WARPS_PER_BLOCK 8
#define NTHREADS (WARPS_PER_BLOCK * 32)
#define ROWS_PER_BLOCK (WARPS_PER_BLOCK * 2)      // 2 rows per warp
#define NBLOCKS (BATCH / ROWS_PER_BLOCK)          // 1024
#define BOFF ((2 + 2 * STEPS) * LAT)              // 4224: bias offset in row

// scratch for deterministic single-kernel loss reduction (no allocations allowed)
__device__ float g_partials[NBLOCKS];
__device__ unsigned int g_count = 0;   // ticket counter; last block resets to 0

__global__ void __launch_bounds__(NTHREADS)
planar_flow_kernel(const float* __restrict__ in,
                   const float* __restrict__ noise,
                   float* __restrict__ out, int out_size)
{
    const int warp = threadIdx.x >> 5;
    const int lane = threadIdx.x & 31;
    const int h    = lane & 15;                    // position within my row's 16-lane group
    const int row  = blockIdx.x * ROWS_PER_BLOCK + warp * 2 + (lane >> 4);

    const float*  rp  = in + (size_t)row * IN_W;   // row*17024B: 16B aligned
    const float4* rp4 = (const float4*)rp;

    // --- z0 = mu + noise * exp(0.5*logsigma2), 4 elements per lane ---
    float4 mu = rp4[h];                                            // floats [0,64)
    float4 ls = rp4[16 + h];                                       // floats [64,128)
    float4 nz = ((const float4*)(noise + (size_t)row * LAT))[h];

    float4 z;
    z.x = mu.x + nz.x * __expf(0.5f * ls.x);
    z.y = mu.y + nz.y * __expf(0.5f * ls.y);
    z.z = mu.z + nz.z * __expf(0.5f * ls.z);
    z.w = mu.w + nz.w * __expf(0.5f * ls.w);

    float kl = -0.5f * (nz.x*nz.x + nz.y*nz.y + nz.z*nz.z + nz.w*nz.w
                        + ls.x + ls.y + ls.z + ls.w);

    // 32 biases per row, held as 2 regs per lane within the 16-lane group
    float bias_lo = rp[BOFF + h];
    float bias_hi = rp[BOFF + 16 + h];

    const float4* U4 = (const float4*)(rp + 2 * LAT);              // stride 16 float4 per step
    const float4* W4 = (const float4*)(rp + (2 + STEPS) * LAT);

    float4 u = U4[h];
    float4 w = W4[h];

    float logacc = 0.0f;   // warp-half-uniform after butterflies

    #pragma unroll 4
    for (int s = 0; s < STEPS; s++) {
        // prefetch next step's u,w (512B per load instruction, covers both rows)
        int sn = (s + 1 < STEPS) ? (s + 1) : s;
        float4 un = U4[sn * 16 + h];
        float4 wn = W4[sn * 16 + h];

        float hl = w.x*z.x + w.y*z.y + w.z*z.z + w.w*z.w;   // partial w.z
        float ul = u.x*w.x + u.y*w.y + u.z*w.z + u.w*w.w;   // partial u.w

        // butterfly within each 16-lane (per-row) group
        #pragma unroll
        for (int o = 8; o > 0; o >>= 1) {
            hl += __shfl_xor_sync(0xffffffffu, hl, o);
            ul += __shfl_xor_sync(0xffffffffu, ul, o);
        }

        // bias for step s of THIS lane's row
        float bsel = (s < 16) ? bias_lo : bias_hi;
        float bb = __shfl_sync(0xffffffffu, bsel, (lane & 16) | (s & 15));

        // tanh via fast exp: t = 1 - 2/(e^{2x}+1); correct limits at +/-inf
        float e = __expf(2.0f * (hl + bb));
        float t = 1.0f - __fdividef(2.0f, e + 1.0f);
        float x = (1.0f - t * t) * ul + 1.0f;
        logacc -= __logf(fabsf(x));

        z.x += u.x * t;  z.y += u.y * t;
        z.z += u.z * t;  z.w += u.w * t;

        u = un; w = wn;
    }

    // coalesced float4 z write
    ((float4*)(out + (size_t)row * LAT))[h] = z;

    // reduce kl within the 16-lane row group
    #pragma unroll
    for (int o = 8; o > 0; o >>= 1)
        kl += __shfl_xor_sync(0xffffffffu, kl, o);

    float rt = kl + logacc;                     // per-row term, uniform per half-warp
    rt += __shfl_xor_sync(0xffffffffu, rt, 16); // sum of the warp's two rows

    __shared__ float sacc[WARPS_PER_BLOCK];
    __shared__ bool is_last;
    if (lane == 0) sacc[warp] = rt;
    __syncthreads();
    if (threadIdx.x == 0) {
        float sum = 0.0f;
        #pragma unroll
        for (int i = 0; i < WARPS_PER_BLOCK; i++) sum += sacc[i];
        g_partials[blockIdx.x] = sum;
        __threadfence();
        unsigned int tk = atomicAdd(&g_count, 1u);
        is_last = (tk == NBLOCKS - 1);
    }
    __syncthreads();

    // last block reduces all partials over a FIXED tree -> deterministic
    if (is_last) {
        float v = 0.0f;
        for (int i = threadIdx.x; i < NBLOCKS; i += NTHREADS)
            v += g_partials[i];
        #pragma unroll
        for (int o = 16; o > 0; o >>= 1)
            v += __shfl_xor_sync(0xffffffffu, v, o);
        if (lane == 0) sacc[warp] = v;
        __syncthreads();
        if (threadIdx.x == 0) {
            float sum = 0.0f;
            #pragma unroll
            for (int i = 0; i < WARPS_PER_BLOCK; i++) sum += sacc[i];
            out[out_size - 1] = sum * (1.0f / (float)BATCH);
            g_count = 0;   // reset for next graph replay
        }
    }
}

extern "C" void kernel_launch(void* const* d_in, const int* in_sizes, int n_in,
                              void* d_out, int out_size)
{
    const float* in    = (const float*)d_in[0];
    const float* noise = (const float*)d_in[1];
    float*       out   = (float*)d_out;

    planar_flow_kernel<<<NBLOCKS, NTHREADS>>>(in, noise, out, out_size);
}

// round 9
// speedup vs baseline: 1.4956x; 1.0708x over previous
#include <cuda_runtime.h>

#define BATCH 16384
#define STEPS 32
#define LAT   64
#define IN_W  (STEPS * (2 * LAT + 1) + 2 * LAT)   // 4256 floats per row
#define WARPS_PER_BLOCK 8
#define NTHREADS (WARPS_PER_BLOCK * 32)
#define ROWS_PER_BLOCK (WARPS_PER_BLOCK * 2)      // 2 rows per warp
#define NBLOCKS (BATCH / ROWS_PER_BLOCK)          // 1024
#define BOFF ((2 + 2 * STEPS) * LAT)              // 4224: bias offset in row
#define PFD 4                                     // prefetch distance (steps)

// scratch for deterministic single-kernel loss reduction (no allocations allowed)
__device__ float g_partials[NBLOCKS];
__device__ unsigned int g_count = 0;   // ticket counter; last block resets to 0

__global__ void __launch_bounds__(NTHREADS, 4)
planar_flow_kernel(const float* __restrict__ in,
                   const float* __restrict__ noise,
                   float* __restrict__ out, int out_size)
{
    const int warp = threadIdx.x >> 5;
    const int lane = threadIdx.x & 31;
    const int h    = lane & 15;                    // position within my row's 16-lane group
    const int row  = blockIdx.x * ROWS_PER_BLOCK + warp * 2 + (lane >> 4);

    const float*  rp  = in + (size_t)row * IN_W;   // 17024 B/row: 16B aligned
    const float4* rp4 = (const float4*)rp;

    const float4* U4 = (const float4*)(rp + 2 * LAT);              // 16 float4 per step
    const float4* W4 = (const float4*)(rp + (2 + STEPS) * LAT);

    // ---- prime the 4-deep u/w register pipeline FIRST (get DRAM busy early) ----
    float4 ubuf[PFD], wbuf[PFD];
    #pragma unroll
    for (int i = 0; i < PFD; i++) {
        ubuf[i] = U4[i * 16 + h];
        wbuf[i] = W4[i * 16 + h];
    }

    // --- z0 = mu + noise * exp(0.5*logsigma2), 4 elements per lane ---
    float4 mu = rp4[h];                                            // floats [0,64)
    float4 ls = rp4[16 + h];                                       // floats [64,128)
    float4 nz = ((const float4*)(noise + (size_t)row * LAT))[h];

    float4 z;
    z.x = mu.x + nz.x * __expf(0.5f * ls.x);
    z.y = mu.y + nz.y * __expf(0.5f * ls.y);
    z.z = mu.z + nz.z * __expf(0.5f * ls.z);
    z.w = mu.w + nz.w * __expf(0.5f * ls.w);

    float kl = -0.5f * (nz.x*nz.x + nz.y*nz.y + nz.z*nz.z + nz.w*nz.w
                        + ls.x + ls.y + ls.z + ls.w);

    // 32 biases per row, 2 regs per lane within the 16-lane group
    float bias_lo = rp[BOFF + h];
    float bias_hi = rp[BOFF + 16 + h];

    float logacc = 0.0f;

    #pragma unroll
    for (int s = 0; s < STEPS; s++) {
        const int slot = s & (PFD - 1);            // constant after full unroll
        float4 u = ubuf[slot];
        float4 w = wbuf[slot];

        // refill this slot for step s+PFD (issued before the dependent chain)
        if (s + PFD < STEPS) {
            ubuf[slot] = U4[(s + PFD) * 16 + h];
            wbuf[slot] = W4[(s + PFD) * 16 + h];
        }

        float hl = w.x*z.x + w.y*z.y + w.z*z.z + w.w*z.w;   // partial w.z
        float ul = u.x*w.x + u.y*w.y + u.z*w.z + u.w*w.w;   // partial u.w

        // butterfly within each 16-lane (per-row) group
        #pragma unroll
        for (int o = 8; o > 0; o >>= 1) {
            hl += __shfl_xor_sync(0xffffffffu, hl, o);
            ul += __shfl_xor_sync(0xffffffffu, ul, o);
        }

        // bias for step s of THIS lane's row
        float bsel = (s < 16) ? bias_lo : bias_hi;
        float bb = __shfl_sync(0xffffffffu, bsel, (lane & 16) | (s & 15));

        // tanh via fast exp: t = 1 - 2/(e^{2x}+1); correct limits at +/-inf
        float e = __expf(2.0f * (hl + bb));
        float t = 1.0f - __fdividef(2.0f, e + 1.0f);
        float x = (1.0f - t * t) * ul + 1.0f;
        logacc -= __logf(fabsf(x));

        z.x += u.x * t;  z.y += u.y * t;
        z.z += u.z * t;  z.w += u.w * t;
    }

    // coalesced float4 z write
    ((float4*)(out + (size_t)row * LAT))[h] = z;

    // reduce kl within the 16-lane row group
    #pragma unroll
    for (int o = 8; o > 0; o >>= 1)
        kl += __shfl_xor_sync(0xffffffffu, kl, o);

    float rt = kl + logacc;                     // per-row term, uniform per half-warp
    rt += __shfl_xor_sync(0xffffffffu, rt, 16); // sum of the warp's two rows

    __shared__ float sacc[WARPS_PER_BLOCK];
    __shared__ bool is_last;
    if (lane == 0) sacc[warp] = rt;
    __syncthreads();
    if (threadIdx.x == 0) {
        float sum = 0.0f;
        #pragma unroll
        for (int i = 0; i < WARPS_PER_BLOCK; i++) sum += sacc[i];
        g_partials[blockIdx.x] = sum;
        __threadfence();
        unsigned int tk = atomicAdd(&g_count, 1u);
        is_last = (tk == NBLOCKS - 1);
    }
    __syncthreads();

    // last block reduces all partials over a FIXED tree -> deterministic
    if (is_last) {
        float v = 0.0f;
        for (int i = threadIdx.x; i < NBLOCKS; i += NTHREADS)
            v += g_partials[i];
        #pragma unroll
        for (int o = 16; o > 0; o >>= 1)
            v += __shfl_xor_sync(0xffffffffu, v, o);
        if (lane == 0) sacc[warp] = v;
        __syncthreads();
        if (threadIdx.x == 0) {
            float sum = 0.0f;
            #pragma unroll
            for (int i = 0; i < WARPS_PER_BLOCK; i++) sum += sacc[i];
            out[out_size - 1] = sum * (1.0f / (float)BATCH);
            g_count = 0;   // reset for next graph replay
        }
    }
}

extern "C" void kernel_launch(void* const* d_in, const int* in_sizes, int n_in,
                              void* d_out, int out_size)
{
    const float* in    = (const float*)d_in[0];
    const float* noise = (const float*)d_in[1];
    float*       out   = (float*)d_out;

    planar_flow_kernel<<<NBLOCKS, NTHREADS>>>(in, noise, out, out_size);
}

// round 10
// speedup vs baseline: 1.6019x; 1.0711x over previous
#include <cuda_runtime.h>

#define BATCH 16384
#define STEPS 32
#define LAT   64
#define IN_W  (STEPS * (2 * LAT + 1) + 2 * LAT)   // 4256 floats per row
#define WARPS_PER_BLOCK 8
#define NTHREADS (WARPS_PER_BLOCK * 32)
#define ROWS_PER_WARP 4
#define ROWS_PER_BLOCK (WARPS_PER_BLOCK * ROWS_PER_WARP)   // 32
#define NBLOCKS (BATCH / ROWS_PER_BLOCK)                   // 512 -> single wave at 4 blocks/SM
#define BOFF ((2 + 2 * STEPS) * LAT)              // 4224: bias offset in row
#define PFD 2                                     // prefetch distance (steps)

// scratch for deterministic single-kernel loss reduction (no allocations allowed)
__device__ float g_partials[NBLOCKS];
__device__ unsigned int g_count = 0;   // ticket counter; last block resets to 0

__global__ void __launch_bounds__(NTHREADS, 4)
planar_flow_kernel(const float* __restrict__ in,
                   const float* __restrict__ noise,
                   float* __restrict__ out, int out_size)
{
    const int warp = threadIdx.x >> 5;
    const int lane = threadIdx.x & 31;
    const int h    = lane & 7;                     // position within my row's 8-lane group
    const int row  = blockIdx.x * ROWS_PER_BLOCK + warp * ROWS_PER_WARP + (lane >> 3);

    const float*  rp  = in + (size_t)row * IN_W;   // 17024 B/row: 16B aligned
    const float4* rp4 = (const float4*)rp;

    const float4* U4 = (const float4*)(rp + 2 * LAT);              // 16 float4 per step
    const float4* W4 = (const float4*)(rp + (2 + STEPS) * LAT);

    // ---- prime the 2-deep u/w register pipeline FIRST (get DRAM busy early) ----
    // lane h covers floats [4h,4h+4) and [32+4h,32+4h+4): each LDG.128 is a
    // fully-contiguous 128B segment per row.
    float4 uA[PFD], uB[PFD], wA[PFD], wB[PFD];
    #pragma unroll
    for (int i = 0; i < PFD; i++) {
        uA[i] = U4[i * 16 + h];
        uB[i] = U4[i * 16 + 8 + h];
        wA[i] = W4[i * 16 + h];
        wB[i] = W4[i * 16 + 8 + h];
    }

    // --- z0 = mu + noise * exp(0.5*logsigma2), 8 elements per lane ---
    float4 muA = rp4[h],        muB = rp4[8 + h];        // floats [0,64)
    float4 lsA = rp4[16 + h],   lsB = rp4[24 + h];       // floats [64,128)
    const float4* np4 = (const float4*)(noise + (size_t)row * LAT);
    float4 nzA = np4[h],        nzB = np4[8 + h];

    float4 zA, zB;
    zA.x = muA.x + nzA.x * __expf(0.5f * lsA.x);
    zA.y = muA.y + nzA.y * __expf(0.5f * lsA.y);
    zA.z = muA.z + nzA.z * __expf(0.5f * lsA.z);
    zA.w = muA.w + nzA.w * __expf(0.5f * lsA.w);
    zB.x = muB.x + nzB.x * __expf(0.5f * lsB.x);
    zB.y = muB.y + nzB.y * __expf(0.5f * lsB.y);
    zB.z = muB.z + nzB.z * __expf(0.5f * lsB.z);
    zB.w = muB.w + nzB.w * __expf(0.5f * lsB.w);

    float kl = -0.5f * (nzA.x*nzA.x + nzA.y*nzA.y + nzA.z*nzA.z + nzA.w*nzA.w
                      + nzB.x*nzB.x + nzB.y*nzB.y + nzB.z*nzB.z + nzB.w*nzB.w
                      + lsA.x + lsA.y + lsA.z + lsA.w
                      + lsB.x + lsB.y + lsB.z + lsB.w);

    // 32 biases per row, 4 regs per lane within the 8-lane group:
    // bias_r[j] = bias[j*8 + h]
    float bias_r[4];
    #pragma unroll
    for (int j = 0; j < 4; j++) bias_r[j] = rp[BOFF + j * 8 + h];

    float logacc = 0.0f;

    #pragma unroll
    for (int s = 0; s < STEPS; s++) {
        const int slot = s & (PFD - 1);            // constant after full unroll
        float4 ua = uA[slot], ub = uB[slot];
        float4 wa = wA[slot], wb = wB[slot];

        // refill this slot for step s+PFD (issued before the dependent chain)
        if (s + PFD < STEPS) {
            uA[slot] = U4[(s + PFD) * 16 + h];
            uB[slot] = U4[(s + PFD) * 16 + 8 + h];
            wA[slot] = W4[(s + PFD) * 16 + h];
            wB[slot] = W4[(s + PFD) * 16 + 8 + h];
        }

        // bias broadcast is off the critical chain; start it early
        float bb = __shfl_sync(0xffffffffu, bias_r[s >> 3], (lane & 24) | (s & 7));

        // balanced product trees (depth ~3) for partials
        float hl = ((wa.x*zA.x + wa.y*zA.y) + (wa.z*zA.z + wa.w*zA.w))
                 + ((wb.x*zB.x + wb.y*zB.y) + (wb.z*zB.z + wb.w*zB.w));
        float ul = ((ua.x*wa.x + ua.y*wa.y) + (ua.z*wa.z + ua.w*wa.w))
                 + ((ub.x*wb.x + ub.y*wb.y) + (ub.z*wb.z + ub.w*wb.w));

        // 3-level butterfly within each 8-lane (per-row) group
        #pragma unroll
        for (int o = 4; o > 0; o >>= 1) {
            hl += __shfl_xor_sync(0xffffffffu, hl, o);
            ul += __shfl_xor_sync(0xffffffffu, ul, o);
        }

        // tanh via fast exp: t = 1 - 2/(e^{2x}+1); correct limits at +/-inf
        float e = __expf(2.0f * (hl + bb));
        float t = 1.0f - __fdividef(2.0f, e + 1.0f);
        float x = (1.0f - t * t) * ul + 1.0f;
        logacc -= __logf(fabsf(x));

        zA.x += ua.x * t;  zA.y += ua.y * t;  zA.z += ua.z * t;  zA.w += ua.w * t;
        zB.x += ub.x * t;  zB.y += ub.y * t;  zB.z += ub.z * t;  zB.w += ub.w * t;
    }

    // coalesced float4 z writes (contiguous 128B per row per instruction)
    float4* op4 = (float4*)(out + (size_t)row * LAT);
    op4[h]     = zA;
    op4[8 + h] = zB;

    // reduce kl within the 8-lane row group
    #pragma unroll
    for (int o = 4; o > 0; o >>= 1)
        kl += __shfl_xor_sync(0xffffffffu, kl, o);

    float rt = kl + logacc;                     // per-row term, uniform per 8-lane group
    rt += __shfl_xor_sync(0xffffffffu, rt, 8);  // sum the warp's 4 rows
    rt += __shfl_xor_sync(0xffffffffu, rt, 16);

    __shared__ float sacc[WARPS_PER_BLOCK];
    __shared__ bool is_last;
    if (lane == 0) sacc[warp] = rt;
    __syncthreads();
    if (threadIdx.x == 0) {
        float sum = 0.0f;
        #pragma unroll
        for (int i = 0; i < WARPS_PER_BLOCK; i++) sum += sacc[i];
        g_partials[blockIdx.x] = sum;
        __threadfence();
        unsigned int tk = atomicAdd(&g_count, 1u);
        is_last = (tk == NBLOCKS - 1);
    }
    __syncthreads();

    // last block reduces all partials over a FIXED tree -> deterministic
    if (is_last) {
        float v = 0.0f;
        #pragma unroll
        for (int i = threadIdx.x; i < NBLOCKS; i += NTHREADS)
            v += g_partials[i];
        #pragma unroll
        for (int o = 16; o > 0; o >>= 1)
            v += __shfl_xor_sync(0xffffffffu, v, o);
        if (lane == 0) sacc[warp] = v;
        __syncthreads();
        if (threadIdx.x == 0) {
            float sum = 0.0f;
            #pragma unroll
            for (int i = 0; i < WARPS_PER_BLOCK; i++) sum += sacc[i];
            out[out_size - 1] = sum * (1.0f / (float)BATCH);
            g_count = 0;   // reset for next graph replay
        }
    }
}

extern "C" void kernel_launch(void* const* d_in, const int* in_sizes, int n_in,
                              void* d_out, int out_size)
{
    const float* in    = (const float*)d_in[0];
    const float* noise = (const float*)d_in[1];
    float*       out   = (float*)d_out;

    planar_flow_kernel<<<NBLOCKS, NTHREADS>>>(in, noise, out, out_size);
}